// round 2
// baseline (speedup 1.0000x reference)
#include <cuda_runtime.h>
#include <math.h>

// Problem constants
#define BB 128      // batch
#define TT 128      // time
#define DD 300      // word dim
#define HH 2048     // hidden
#define H4 8192     // 4*hidden

// Scratch (device globals — no allocation in kernel_launch).
// Zpre layout: [t][b][4H]  (row r = t*BB + b), 512 MB.
__device__ float g_Zpre[(size_t)TT * BB * H4];
// Cell state, [b][H]. Fully overwritten by step0 each launch -> deterministic.
__device__ float g_c[BB * HH];

// ---------------------------------------------------------------------------
// Phase 1: Zpre[r][n] = X_row(r)[k] * W[k][n] + bias[n],  r = t*BB + b
//          M = 16384, N = 8192, K = 300
// Tiled fp32 GEMM: BM=64, BN=64, BK=16, 256 threads, 4x4 per thread.
// ---------------------------------------------------------------------------
__global__ void __launch_bounds__(256) phase1_gemm(
    const float* __restrict__ X,      // [B][T][D]
    const float* __restrict__ W,      // [D+H][4H]
    const float* __restrict__ bias)   // [4H]
{
    const int BM = 64, BN = 64, BK = 16;
    __shared__ float As[BK][BM + 1];  // [k][m], +1 pad
    __shared__ float Bs[BK][BN];      // [k][n]

    const int row0 = blockIdx.y * BM;
    const int col0 = blockIdx.x * BN;
    const int tid  = threadIdx.x;
    const int tx   = tid & 15;        // col group (4 cols)
    const int ty   = tid >> 4;        // row group (4 rows)

    float acc[4][4] = {};

    for (int k0 = 0; k0 < DD; k0 += BK) {
        // Load A tile: 64x16, 4 elems/thread, coalesced along k.
        #pragma unroll
        for (int i = 0; i < 4; i++) {
            int e = tid + i * 256;
            int k = e & 15;
            int m = e >> 4;
            int kk = k0 + k;
            float v = 0.f;
            if (kk < DD) {
                int r = row0 + m;
                int b = r & (BB - 1);
                int t = r >> 7;
                v = X[((size_t)b * TT + t) * DD + kk];
            }
            As[k][m] = v;
        }
        // Load B tile: 16x64, 4 elems/thread, coalesced along n.
        #pragma unroll
        for (int i = 0; i < 4; i++) {
            int e = tid + i * 256;
            int k = e >> 6;
            int n = e & 63;
            int kk = k0 + k;
            Bs[k][n] = (kk < DD) ? W[(size_t)kk * H4 + col0 + n] : 0.f;
        }
        __syncthreads();

        #pragma unroll
        for (int kk = 0; kk < BK; kk++) {
            float a[4], bf[4];
            #pragma unroll
            for (int i = 0; i < 4; i++) a[i]  = As[kk][ty * 4 + i];
            #pragma unroll
            for (int j = 0; j < 4; j++) bf[j] = Bs[kk][tx * 4 + j];
            #pragma unroll
            for (int i = 0; i < 4; i++)
                #pragma unroll
                for (int j = 0; j < 4; j++)
                    acc[i][j] += a[i] * bf[j];
        }
        __syncthreads();
    }

    #pragma unroll
    for (int i = 0; i < 4; i++) {
        size_t r = row0 + ty * 4 + i;
        #pragma unroll
        for (int j = 0; j < 4; j++) {
            int n = col0 + tx * 4 + j;
            g_Zpre[r * H4 + n] = acc[i][j] + bias[n];
        }
    }
}

// ---------------------------------------------------------------------------
// Step 0: no recurrent GEMM (h0 = 0). z = Zpre[0]; c = i*g; h = o*tanh(c).
// Also initializes g_c (overwrites all entries -> no zero pass needed).
// ---------------------------------------------------------------------------
__global__ void __launch_bounds__(256) lstm_step0(float* out)
{
    int idx = blockIdx.x * blockDim.x + threadIdx.x;   // [0, B*H)
    int b = idx >> 11;          // / 2048
    int n = idx & (HH - 1);
    const float* zp = g_Zpre + (size_t)b * H4;         // row r = b for t=0
    float zi = zp[0 * HH + n];
    float zf = zp[1 * HH + n];  (void)zf;              // f*c0 = 0
    float zg = zp[2 * HH + n];
    float zo = zp[3 * HH + n];
    float ig = 1.f / (1.f + expf(-zi));
    float gg = tanhf(zg);
    float og = 1.f / (1.f + expf(-zo));
    float cn = ig * gg;
    g_c[idx] = cn;
    out[(size_t)b * TT * HH + n] = og * tanhf(cn);
}

// ---------------------------------------------------------------------------
// Step t (t >= 1), fully fused:
//   z = h_prev @ Wh + Zpre[t]   (h_prev = out[:, t-1, :])
//   gates -> c update -> h = out[:, t, :]
// Grid: 128 blocks (16 H-cols each). Block GEMM tile: 128 x 64 (4 gates x 16),
// K = 2048, BK = 32, 256 threads, 8x4 per-thread tile.
// ---------------------------------------------------------------------------
__global__ void __launch_bounds__(256) lstm_step(
    const float* __restrict__ W,   // [D+H][4H]
    float* out,                    // [B][T][H] (h history lives here)
    int t)
{
    const int BK = 32;
    // smem: main-loop tiles overlap with the z exchange buffer.
    //   As: [32][132] (transposed h tile, padded)  = 4224 floats
    //   Bs: [32][64]                               = 2048 floats
    //   zs: [128][68]                              = 8704 floats (max)
    __shared__ float smem[128 * 68];
    float (*As)[132] = reinterpret_cast<float (*)[132]>(smem);
    float (*Bs)[64]  = reinterpret_cast<float (*)[64]>(smem + 32 * 132);

    const int n0  = blockIdx.x * 16;   // H-column base for this block
    const int tid = threadIdx.x;
    const int tx  = tid & 15;          // col group: 4 z-cols
    const int ty  = tid >> 4;          // row group: 8 batch rows

    const float* hprev = out + (size_t)(t - 1) * HH;   // + b*T*H + k

    float acc[8][4] = {};

    for (int k0 = 0; k0 < HH; k0 += BK) {
        // Load A (h_prev) tile 128x32 as float4 along k, store transposed.
        #pragma unroll
        for (int i = 0; i < 4; i++) {
            int e  = tid + i * 256;
            int b  = e >> 3;
            int k4 = e & 7;
            float4 v = *reinterpret_cast<const float4*>(
                hprev + (size_t)b * TT * HH + k0 + k4 * 4);
            As[k4 * 4 + 0][b] = v.x;
            As[k4 * 4 + 1][b] = v.y;
            As[k4 * 4 + 2][b] = v.z;
            As[k4 * 4 + 3][b] = v.w;
        }
        // Load B (Wh) tile 32x64: col c = gate*16 + j -> global gate*2048+n0+j.
        #pragma unroll
        for (int i = 0; i < 8; i++) {
            int e    = tid + i * 256;
            int kk   = e >> 6;
            int c    = e & 63;
            int gate = c >> 4;
            int j    = c & 15;
            Bs[kk][c] = W[(size_t)(DD + k0 + kk) * H4 + gate * HH + n0 + j];
        }
        __syncthreads();

        #pragma unroll
        for (int kk = 0; kk < BK; kk++) {
            float4 a0 = *reinterpret_cast<const float4*>(&As[kk][ty * 8]);
            float4 a1 = *reinterpret_cast<const float4*>(&As[kk][ty * 8 + 4]);
            float4 bv = *reinterpret_cast<const float4*>(&Bs[kk][tx * 4]);
            float a[8] = {a0.x, a0.y, a0.z, a0.w, a1.x, a1.y, a1.z, a1.w};
            float bf[4] = {bv.x, bv.y, bv.z, bv.w};
            #pragma unroll
            for (int i = 0; i < 8; i++)
                #pragma unroll
                for (int j = 0; j < 4; j++)
                    acc[i][j] += a[i] * bf[j];
        }
        __syncthreads();
    }

    // Exchange z tile through smem so each thread can combine all 4 gates.
    float (*zs)[68] = reinterpret_cast<float (*)[68]>(smem);
    #pragma unroll
    for (int i = 0; i < 8; i++) {
        *reinterpret_cast<float4*>(&zs[ty * 8 + i][tx * 4]) =
            make_float4(acc[i][0], acc[i][1], acc[i][2], acc[i][3]);
    }
    __syncthreads();

    const float* zp = g_Zpre + (size_t)t * BB * H4;
    const int j = tid & 15;
    const int n = n0 + j;
    #pragma unroll
    for (int i = 0; i < 8; i++) {
        int b = (tid >> 4) * 8 + i;
        const float* zpb = zp + (size_t)b * H4;
        float zi = zs[b][ 0 + j] + zpb[0 * HH + n];
        float zf = zs[b][16 + j] + zpb[1 * HH + n];
        float zg = zs[b][32 + j] + zpb[2 * HH + n];
        float zo = zs[b][48 + j] + zpb[3 * HH + n];
        float ig = 1.f / (1.f + expf(-zi));
        float fg = 1.f / (1.f + expf(-zf));
        float gg = tanhf(zg);
        float og = 1.f / (1.f + expf(-zo));
        int cidx = b * HH + n;
        float cn = fg * g_c[cidx] + ig * gg;
        g_c[cidx] = cn;
        out[(size_t)b * TT * HH + (size_t)t * HH + n] = og * tanhf(cn);
    }
}

// ---------------------------------------------------------------------------
// Launch: phase1 GEMM, then 128 sequential step kernels (graph-captured).
// ---------------------------------------------------------------------------
extern "C" void kernel_launch(void* const* d_in, const int* in_sizes, int n_in,
                              void* d_out, int out_size)
{
    (void)in_sizes; (void)n_in; (void)out_size;
    const float* X    = (const float*)d_in[0];   // embed_words [B][T][D]
    // d_in[1]: lengths — unused (reference discards the gather)
    const float* W    = (const float*)d_in[2];   // [D+H][4H]
    const float* bias = (const float*)d_in[3];   // [4H]
    float* out        = (float*)d_out;           // [B][T][H]

    // Phase 1: input projection for all timesteps.
    dim3 g1(H4 / 64, (BB * TT) / 64);            // 128 x 256 blocks
    phase1_gemm<<<g1, 256>>>(X, W, bias);

    // Step 0 (no recurrence; also initializes g_c).
    lstm_step0<<<(BB * HH) / 256, 256>>>(out);

    // Steps 1..T-1.
    for (int t = 1; t < TT; t++) {
        lstm_step<<<HH / 16, 256>>>(W, out, t);
    }
}

// round 7
// speedup vs baseline: 3.1339x; 3.1339x over previous
#include <cuda_runtime.h>
#include <cuda_bf16.h>
#include <cstdint>
#include <math.h>

#define BB 128
#define TT 128
#define DD 300
#define HH 2048
#define H4 8192
#define KP1 320

// ---- device scratch (no allocation in kernel_launch) ----
__device__ float g_Zpre[(size_t)TT * BB * H4];   // x@W1 + bias, [t*BB+b][4H]
__device__ float g_c[BB * HH];
__device__ __nv_bfloat16 g_Xhi[(size_t)TT * BB * KP1];
__device__ __nv_bfloat16 g_Xlo[(size_t)TT * BB * KP1];
__device__ __nv_bfloat16 g_W1hi[(size_t)H4 * KP1];   // W[0:300,:]^T padded, [n][k]
__device__ __nv_bfloat16 g_W1lo[(size_t)H4 * KP1];
__device__ __nv_bfloat16 g_Whhi[(size_t)H4 * HH];    // W[300:,:]^T, [n][k]
__device__ __nv_bfloat16 g_Whlo[(size_t)H4 * HH];
__device__ __nv_bfloat16 g_hhi[2][BB * HH];          // double-buffered h split
__device__ __nv_bfloat16 g_hlo[2][BB * HH];

// ---- helpers (base sm_100 ISA only: cp.async + ldmatrix + mma.sync) ----
__device__ __forceinline__ uint32_t smem_u32(const void* p) {
    uint32_t a;
    asm("{ .reg .u64 t; cvta.to.shared.u64 t, %1; cvt.u32.u64 %0, t; }" : "=r"(a) : "l"(p));
    return a;
}
__device__ __forceinline__ void cpa16(uint32_t dst, const void* src) {
    asm volatile("cp.async.cg.shared.global [%0], [%1], 16;" :: "r"(dst), "l"(src) : "memory");
}
#define CP_COMMIT() asm volatile("cp.async.commit_group;" ::: "memory")
#define CP_WAIT1()  asm volatile("cp.async.wait_group 1;" ::: "memory")
#define CP_WAIT0()  asm volatile("cp.async.wait_group 0;" ::: "memory")

__device__ __forceinline__ void ldsm4(uint32_t* r, uint32_t addr) {
    asm volatile("ldmatrix.sync.aligned.m8n8.x4.shared.b16 {%0,%1,%2,%3}, [%4];"
                 : "=r"(r[0]), "=r"(r[1]), "=r"(r[2]), "=r"(r[3]) : "r"(addr));
}
__device__ __forceinline__ void mma_bf16(float* c, const uint32_t* a,
                                         uint32_t b0, uint32_t b1) {
    asm volatile("mma.sync.aligned.m16n8k16.row.col.f32.bf16.bf16.f32 "
                 "{%0,%1,%2,%3}, {%4,%5,%6,%7}, {%8,%9}, {%0,%1,%2,%3};"
                 : "+f"(c[0]), "+f"(c[1]), "+f"(c[2]), "+f"(c[3])
                 : "r"(a[0]), "r"(a[1]), "r"(a[2]), "r"(a[3]), "r"(b0), "r"(b1));
}
__device__ __forceinline__ uint32_t sw128(uint32_t x) { return x ^ ((x >> 3) & 0x70); }

// smem chunk buffer: A(64 rows x 128B) hi/lo + B(128 rows x 128B) hi/lo
#define OFF_AHI 0
#define OFF_ALO 8192
#define OFF_BHI 16384
#define OFF_BLO 32768
#define BUF_SZ  49152
#define SMEM_BYTES (1024 + 2 * BUF_SZ)

// ---- activations (overflow-safe) ----
__device__ __forceinline__ float sigf(float x) {
    return __fdividef(1.f, 1.f + __expf(-x));
}
__device__ __forceinline__ float tanhfast(float x) {
    float e = __expf(-2.f * fabsf(x));
    return copysignf(__fdividef(1.f - e, 1.f + e), x);
}
__device__ __forceinline__ void split2(float v, __nv_bfloat16& hi, __nv_bfloat16& lo) {
    hi = __float2bfloat16(v);
    lo = __float2bfloat16(v - __bfloat162float(hi));
}

// ---- prep: split X into bf16 hi/lo rows [r=t*BB+b][KP1], zero-padded K ----
__global__ void __launch_bounds__(KP1) convert_X(const float* __restrict__ X)
{
    int r = blockIdx.x, k = threadIdx.x;
    int t = r >> 7, b = r & (BB - 1);
    float v = (k < DD) ? X[((size_t)b * TT + t) * DD + k] : 0.f;
    __nv_bfloat16 hi, lo; split2(v, hi, lo);
    size_t o = (size_t)r * KP1 + k;
    g_Xhi[o] = hi; g_Xlo[o] = lo;
}

// ---- prep: transpose + split W into W1t [n][0..320) and Wht [n][0..2048) ----
__global__ void __launch_bounds__(256) transW(const float* __restrict__ W)
{
    __shared__ float tile[32][33];
    int tx = threadIdx.x, ty = threadIdx.y;   // 32 x 8
    int k_t = blockIdx.x * 32;                // 74 tiles over kk in [0,2368)
    int n_t = blockIdx.y * 32;
    #pragma unroll
    for (int i = 0; i < 4; i++) {
        int kk = k_t + ty + i * 8;
        float v = 0.f;
        if (kk < KP1) { if (kk < DD) v = W[(size_t)kk * H4 + n_t + tx]; }
        else           v = W[(size_t)(kk - 20) * H4 + n_t + tx];   // kk-320+300
        tile[ty + i * 8][tx] = v;
    }
    __syncthreads();
    #pragma unroll
    for (int i = 0; i < 4; i++) {
        int n  = n_t + ty + i * 8;
        int kk = k_t + tx;
        __nv_bfloat16 hi, lo; split2(tile[tx][ty + i * 8], hi, lo);
        if (kk < KP1) { size_t o = (size_t)n * KP1 + kk;        g_W1hi[o] = hi; g_W1lo[o] = lo; }
        else          { size_t o = (size_t)n * HH + (kk - KP1); g_Whhi[o] = hi; g_Whlo[o] = lo; }
    }
}

// ---- step 0: h0 = 0 -> c = i*g, h = o*tanh(c); also seeds g_h[0] ----
__global__ void __launch_bounds__(256) lstm_step0(float* __restrict__ out)
{
    int idx = blockIdx.x * blockDim.x + threadIdx.x;   // [0, B*H)
    int b = idx >> 11, n = idx & (HH - 1);
    const float* zp = g_Zpre + (size_t)b * H4;          // r = b at t=0
    float cn = sigf(zp[n]) * tanhfast(zp[2 * HH + n]);
    float h  = sigf(zp[3 * HH + n]) * tanhfast(cn);
    g_c[idx] = cn;
    out[(size_t)b * TT * HH + n] = h;
    __nv_bfloat16 hi, lo; split2(h, hi, lo);
    g_hhi[0][idx] = hi; g_hlo[0][idx] = lo;
}

// ---------------------------------------------------------------------------
// bf16 mma.sync GEMM, tile M=64 x N=128, K chunks of 64, hi/lo 3-product split.
// P1: Zpre tile = X @ W1t^T + bias.   step: z = h @ Wht^T + fused LSTM epilogue.
// 8 warps = 2m x 4n, warp tile 32x32, acc[2][4][4].
// ---------------------------------------------------------------------------
template<bool P1>
__global__ void __launch_bounds__(256, 1) mma_kernel(
    float* __restrict__ out, const float* __restrict__ bias, int t)
{
    extern __shared__ __align__(16) char dsm[];
    const uint32_t raw  = smem_u32(dsm);
    const uint32_t base = (raw + 1023) & ~1023u;
    float* zs = (float*)(dsm + (base - raw));      // reused post-GEMM, pitch 132

    const int tid = threadIdx.x, wid = tid >> 5, lane = tid & 31;
    const int wm = wid >> 2, wn = wid & 3;         // warp grid 2m x 4n
    const int NC = P1 ? 5 : 32;
    const int nb = blockIdx.x;                     // n tile
    const int bm = blockIdx.y;                     // m tile

    const __nv_bfloat16 *Ahi, *Alo, *Bhi, *Blo;
    size_t astr, bstr;
    if (P1) {
        size_t r0 = (size_t)bm * 64;
        Ahi = g_Xhi + r0 * KP1; Alo = g_Xlo + r0 * KP1; astr = KP1;
        Bhi = g_W1hi; Blo = g_W1lo; bstr = KP1;
    } else {
        int pb = (t - 1) & 1;
        Ahi = g_hhi[pb] + (size_t)bm * 64 * HH;
        Alo = g_hlo[pb] + (size_t)bm * 64 * HH;
        astr = HH;
        Bhi = g_Whhi; Blo = g_Whlo; bstr = HH;
    }

    auto load_chunk = [&](int j) {
        uint32_t bp = base + (j & 1) * BUF_SZ;
        int kb = j * 128;                          // K byte offset (64 bf16)
        #pragma unroll
        for (int i = 0; i < 2; i++) {              // A: 64 rows x 8 x16B
            int e = tid + i * 256; int row = e >> 3, q = e & 7;
            uint32_t so = sw128((uint32_t)(row * 128 + q * 16));
            size_t go = (size_t)row * astr * 2 + kb + q * 16;
            cpa16(bp + OFF_AHI + so, (const char*)Ahi + go);
            cpa16(bp + OFF_ALO + so, (const char*)Alo + go);
        }
        #pragma unroll
        for (int i = 0; i < 4; i++) {              // B: 128 rows x 8 x16B
            int e = tid + i * 256; int c = e >> 3, q = e & 7;
            int ng = P1 ? (nb * 128 + c) : ((c >> 5) * HH + nb * 32 + (c & 31));
            uint32_t so = sw128((uint32_t)(c * 128 + q * 16));
            size_t go = (size_t)ng * bstr * 2 + kb + q * 16;
            cpa16(bp + OFF_BHI + so, (const char*)Bhi + go);
            cpa16(bp + OFF_BLO + so, (const char*)Blo + go);
        }
    };

    float acc[2][4][4];
    #pragma unroll
    for (int i = 0; i < 2; i++)
        #pragma unroll
        for (int j = 0; j < 4; j++)
            #pragma unroll
            for (int k = 0; k < 4; k++) acc[i][j][k] = 0.f;

    load_chunk(0); CP_COMMIT();

    for (int j = 0; j < NC; j++) {
        if (j + 1 < NC) { load_chunk(j + 1); CP_COMMIT(); CP_WAIT1(); }
        else            { CP_WAIT0(); }
        __syncthreads();

        uint32_t bp = base + (j & 1) * BUF_SZ;
        #pragma unroll
        for (int ks = 0; ks < 4; ks++) {
            const uint32_t colb = (uint32_t)(ks * 32 + (lane >> 4) * 16);
            uint32_t a_hi[2][4], a_lo[2][4];
            #pragma unroll
            for (int i = 0; i < 2; i++) {
                uint32_t off = sw128((uint32_t)((wm * 32 + i * 16 + (lane & 15)) * 128) + colb);
                ldsm4(a_hi[i], bp + OFF_AHI + off);
                ldsm4(a_lo[i], bp + OFF_ALO + off);
            }
            uint32_t bh[2][4], bl[2][4];
            #pragma unroll
            for (int jp = 0; jp < 2; jp++) {
                uint32_t off = sw128((uint32_t)((wn * 32 + jp * 16 + (lane & 15)) * 128) + colb);
                ldsm4(bh[jp], bp + OFF_BHI + off);
                ldsm4(bl[jp], bp + OFF_BLO + off);
            }
            #pragma unroll
            for (int i = 0; i < 2; i++)
                #pragma unroll
                for (int jj = 0; jj < 4; jj++) {
                    int jp = jj >> 1, sel = jj & 1;
                    uint32_t bh0 = bh[jp][sel], bh1 = bh[jp][sel + 2];
                    uint32_t bl0 = bl[jp][sel], bl1 = bl[jp][sel + 2];
                    mma_bf16(acc[i][jj], a_hi[i], bh0, bh1);
                    mma_bf16(acc[i][jj], a_lo[i], bh0, bh1);
                    mma_bf16(acc[i][jj], a_hi[i], bl0, bl1);
                }
        }
        __syncthreads();
    }

    // registers -> zs[row][col], pitch 132
    #pragma unroll
    for (int i = 0; i < 2; i++)
        #pragma unroll
        for (int jj = 0; jj < 4; jj++)
            #pragma unroll
            for (int k4 = 0; k4 < 4; k4++) {
                int r = wm * 32 + i * 16 + (lane >> 2) + ((k4 >> 1) ? 8 : 0);
                int c = wn * 32 + jj * 8 + (lane & 3) * 2 + (k4 & 1);
                zs[r * 132 + c] = acc[i][jj][k4];
            }
    __syncthreads();

    if (P1) {
        size_t r0 = (size_t)bm * 64;
        int nl = tid & 127, rg = tid >> 7;
        int n0 = nb * 128;
        float bz = bias[n0 + nl];
        #pragma unroll 4
        for (int i = 0; i < 32; i++) {
            int rl = rg * 32 + i;
            g_Zpre[(r0 + rl) * H4 + n0 + nl] = zs[rl * 132 + nl] + bz;
        }
    } else {
        int nl = lane;
        int n = nb * 32 + nl;
        #pragma unroll 2
        for (int it = 0; it < 8; it++) {
            int bl = wid + it * 8;                  // local row 0..63
            int b = bm * 64 + bl;
            const float* zp = g_Zpre + ((size_t)t * BB + b) * H4;
            float vi = zs[bl * 132 +  0 + nl] + zp[0 * HH + n];
            float vf = zs[bl * 132 + 32 + nl] + zp[1 * HH + n];
            float vg = zs[bl * 132 + 64 + nl] + zp[2 * HH + n];
            float vo = zs[bl * 132 + 96 + nl] + zp[3 * HH + n];
            float ig = sigf(vi), fg = sigf(vf);
            float gg = tanhfast(vg), og = sigf(vo);
            int ci = b * HH + n;
            float cn = fg * g_c[ci] + ig * gg;
            g_c[ci] = cn;
            float h = og * tanhfast(cn);
            out[(size_t)b * TT * HH + (size_t)t * HH + n] = h;
            __nv_bfloat16 hi, lo; split2(h, hi, lo);
            g_hhi[t & 1][ci] = hi; g_hlo[t & 1][ci] = lo;
        }
    }
}

// ---------------------------------------------------------------------------
extern "C" void kernel_launch(void* const* d_in, const int* in_sizes, int n_in,
                              void* d_out, int out_size)
{
    (void)in_sizes; (void)n_in; (void)out_size;
    const float* X    = (const float*)d_in[0];   // embed_words [B][T][D]
    const float* W    = (const float*)d_in[2];   // [D+H][4H]  (d_in[1]=lengths unused)
    const float* bias = (const float*)d_in[3];   // [4H]
    float* out        = (float*)d_out;           // [B][T][H]

    cudaFuncSetAttribute(mma_kernel<true>,  cudaFuncAttributeMaxDynamicSharedMemorySize, SMEM_BYTES);
    cudaFuncSetAttribute(mma_kernel<false>, cudaFuncAttributeMaxDynamicSharedMemorySize, SMEM_BYTES);

    convert_X<<<TT * BB, KP1>>>(X);
    transW<<<dim3(74, 256), dim3(32, 8)>>>(W);
    mma_kernel<true><<<dim3(64, 256), 256, SMEM_BYTES>>>(nullptr, bias, 0);
    lstm_step0<<<(BB * HH) / 256, 256>>>(out);
    for (int t = 1; t < TT; t++)
        mma_kernel<false><<<dim3(64, 2), 256, SMEM_BYTES>>>(out, nullptr, t);
}

// round 8
// speedup vs baseline: 3.2234x; 1.0286x over previous
#include <cuda_runtime.h>
#include <cuda_bf16.h>
#include <cstdint>
#include <math.h>

#define BB 128
#define TT 128
#define DD 300
#define HH 2048
#define H4 8192
#define KP1 320

// ---- device scratch (no allocation in kernel_launch) ----
__device__ float g_Zpre[(size_t)TT * BB * H4];   // x@W1 + bias, [t*BB+b][4H]
__device__ float g_c[BB * HH];
__device__ __nv_bfloat16 g_Xhi[(size_t)TT * BB * KP1];
__device__ __nv_bfloat16 g_Xlo[(size_t)TT * BB * KP1];
__device__ __nv_bfloat16 g_W1hi[(size_t)H4 * KP1];   // W[0:300,:]^T padded, [n][k]
__device__ __nv_bfloat16 g_W1lo[(size_t)H4 * KP1];
__device__ __nv_bfloat16 g_Whhi[(size_t)H4 * HH];    // W[300:,:]^T, [n][k]
__device__ __nv_bfloat16 g_Whlo[(size_t)H4 * HH];
__device__ __nv_bfloat16 g_hhi[2][BB * HH];          // double-buffered h split
__device__ __nv_bfloat16 g_hlo[2][BB * HH];

// ---- helpers (base sm_100 ISA: cp.async + ldmatrix + mma.sync) ----
__device__ __forceinline__ uint32_t smem_u32(const void* p) {
    uint32_t a;
    asm("{ .reg .u64 t; cvta.to.shared.u64 t, %1; cvt.u32.u64 %0, t; }" : "=r"(a) : "l"(p));
    return a;
}
__device__ __forceinline__ void cpa16(uint32_t dst, const void* src) {
    asm volatile("cp.async.cg.shared.global [%0], [%1], 16;" :: "r"(dst), "l"(src) : "memory");
}
#define CP_COMMIT() asm volatile("cp.async.commit_group;" ::: "memory")
#define CP_WAIT1()  asm volatile("cp.async.wait_group 1;" ::: "memory")
#define CP_WAIT0()  asm volatile("cp.async.wait_group 0;" ::: "memory")

__device__ __forceinline__ void ldsm4(uint32_t* r, uint32_t addr) {
    asm volatile("ldmatrix.sync.aligned.m8n8.x4.shared.b16 {%0,%1,%2,%3}, [%4];"
                 : "=r"(r[0]), "=r"(r[1]), "=r"(r[2]), "=r"(r[3]) : "r"(addr));
}
__device__ __forceinline__ void mma_bf16(float* c, const uint32_t* a,
                                         uint32_t b0, uint32_t b1) {
    asm volatile("mma.sync.aligned.m16n8k16.row.col.f32.bf16.bf16.f32 "
                 "{%0,%1,%2,%3}, {%4,%5,%6,%7}, {%8,%9}, {%0,%1,%2,%3};"
                 : "+f"(c[0]), "+f"(c[1]), "+f"(c[2]), "+f"(c[3])
                 : "r"(a[0]), "r"(a[1]), "r"(a[2]), "r"(a[3]), "r"(b0), "r"(b1));
}
__device__ __forceinline__ uint32_t sw128(uint32_t x) { return x ^ ((x >> 3) & 0x70); }

// smem chunk buffer: A(64 rows x 128B) hi/lo + B(128 rows x 128B) hi/lo
#define OFF_AHI 0
#define OFF_ALO 8192
#define OFF_BHI 16384
#define OFF_BLO 32768
#define BUF_SZ  49152
#define SMEM_BYTES (1024 + 2 * BUF_SZ)

// ---- activations (overflow-safe) ----
__device__ __forceinline__ float sigf(float x) {
    return __fdividef(1.f, 1.f + __expf(-x));
}
__device__ __forceinline__ float tanhfast(float x) {
    float e = __expf(-2.f * fabsf(x));
    return copysignf(__fdividef(1.f - e, 1.f + e), x);
}
__device__ __forceinline__ void split2(float v, __nv_bfloat16& hi, __nv_bfloat16& lo) {
    hi = __float2bfloat16(v);
    lo = __float2bfloat16(v - __bfloat162float(hi));
}

// ---- prep: split X into bf16 hi/lo rows [r=t*BB+b][KP1], zero-padded K ----
__global__ void __launch_bounds__(KP1) convert_X(const float* __restrict__ X)
{
    int r = blockIdx.x, k = threadIdx.x;
    int t = r >> 7, b = r & (BB - 1);
    float v = (k < DD) ? X[((size_t)b * TT + t) * DD + k] : 0.f;
    __nv_bfloat16 hi, lo; split2(v, hi, lo);
    size_t o = (size_t)r * KP1 + k;
    g_Xhi[o] = hi; g_Xlo[o] = lo;
}

// ---- prep: transpose + split W into W1t [n][0..320) and Wht [n][0..2048) ----
__global__ void __launch_bounds__(256) transW(const float* __restrict__ W)
{
    __shared__ float tile[32][33];
    int tx = threadIdx.x, ty = threadIdx.y;   // 32 x 8
    int k_t = blockIdx.x * 32;                // 74 tiles over kk in [0,2368)
    int n_t = blockIdx.y * 32;
    #pragma unroll
    for (int i = 0; i < 4; i++) {
        int kk = k_t + ty + i * 8;
        float v = 0.f;
        if (kk < KP1) { if (kk < DD) v = W[(size_t)kk * H4 + n_t + tx]; }
        else           v = W[(size_t)(kk - 20) * H4 + n_t + tx];   // kk-320+300
        tile[ty + i * 8][tx] = v;
    }
    __syncthreads();
    #pragma unroll
    for (int i = 0; i < 4; i++) {
        int n  = n_t + ty + i * 8;
        int kk = k_t + tx;
        __nv_bfloat16 hi, lo; split2(tile[tx][ty + i * 8], hi, lo);
        if (kk < KP1) { size_t o = (size_t)n * KP1 + kk;        g_W1hi[o] = hi; g_W1lo[o] = lo; }
        else          { size_t o = (size_t)n * HH + (kk - KP1); g_Whhi[o] = hi; g_Whlo[o] = lo; }
    }
}

// ---- step 0: h0 = 0 -> c = i*g, h = o*tanh(c); also seeds g_h[0] ----
__global__ void __launch_bounds__(256) lstm_step0(float* __restrict__ out)
{
    int idx = blockIdx.x * blockDim.x + threadIdx.x;   // [0, B*H)
    int b = idx >> 11, n = idx & (HH - 1);
    const float* zp = g_Zpre + (size_t)b * H4;          // r = b at t=0
    float cn = sigf(zp[n]) * tanhfast(zp[2 * HH + n]);
    float h  = sigf(zp[3 * HH + n]) * tanhfast(cn);
    g_c[idx] = cn;
    out[(size_t)b * TT * HH + n] = h;
    __nv_bfloat16 hi, lo; split2(h, hi, lo);
    g_hhi[0][idx] = hi; g_hlo[0][idx] = lo;
}

// ---------------------------------------------------------------------------
// bf16 mma.sync GEMM, tile M=64 x N=128, K chunks of 64, hi/lo 3-product split.
// 512 threads = 16 warps (4m x 4n), warp tile 16x32, acc[4][4].
// P1: Zpre tile = X @ W1t^T + bias.   step: z = h @ Wht^T + fused LSTM epilogue.
// ---------------------------------------------------------------------------
template<bool P1>
__global__ void __launch_bounds__(512, 1) mma_kernel(
    float* __restrict__ out, const float* __restrict__ bias, int t)
{
    extern __shared__ __align__(16) char dsm[];
    const uint32_t raw  = smem_u32(dsm);
    const uint32_t base = (raw + 1023) & ~1023u;
    float* zs = (float*)(dsm + (base - raw));      // reused post-GEMM, pitch 132

    const int tid = threadIdx.x, wid = tid >> 5, lane = tid & 31;
    const int wm = wid >> 2, wn = wid & 3;         // warp grid 4m x 4n
    const int NC = P1 ? 5 : 32;
    const int nb = blockIdx.x;                     // n tile
    const int bm = blockIdx.y;                     // m tile

    const __nv_bfloat16 *Ahi, *Alo, *Bhi, *Blo;
    size_t astr, bstr;
    if (P1) {
        size_t r0 = (size_t)bm * 64;
        Ahi = g_Xhi + r0 * KP1; Alo = g_Xlo + r0 * KP1; astr = KP1;
        Bhi = g_W1hi; Blo = g_W1lo; bstr = KP1;
    } else {
        int pb = (t - 1) & 1;
        Ahi = g_hhi[pb] + (size_t)bm * 64 * HH;
        Alo = g_hlo[pb] + (size_t)bm * 64 * HH;
        astr = HH;
        Bhi = g_Whhi; Blo = g_Whlo; bstr = HH;
    }

    auto load_chunk = [&](int j) {
        uint32_t bp = base + (j & 1) * BUF_SZ;
        int kb = j * 128;                          // K byte offset (64 bf16)
        {                                          // A: 64 rows x 8 x16B, 512 thr
            int row = tid >> 3, q = tid & 7;
            uint32_t so = sw128((uint32_t)(row * 128 + q * 16));
            size_t go = (size_t)row * astr * 2 + kb + q * 16;
            cpa16(bp + OFF_AHI + so, (const char*)Ahi + go);
            cpa16(bp + OFF_ALO + so, (const char*)Alo + go);
        }
        #pragma unroll
        for (int i = 0; i < 2; i++) {              // B: 128 rows x 8 x16B
            int e = tid + i * 512; int c = e >> 3, q = e & 7;
            int ng = P1 ? (nb * 128 + c) : ((c >> 5) * HH + nb * 32 + (c & 31));
            uint32_t so = sw128((uint32_t)(c * 128 + q * 16));
            size_t go = (size_t)ng * bstr * 2 + kb + q * 16;
            cpa16(bp + OFF_BHI + so, (const char*)Bhi + go);
            cpa16(bp + OFF_BLO + so, (const char*)Blo + go);
        }
    };

    float acc[4][4];
    #pragma unroll
    for (int j = 0; j < 4; j++)
        #pragma unroll
        for (int k = 0; k < 4; k++) acc[j][k] = 0.f;

    load_chunk(0); CP_COMMIT();

    for (int j = 0; j < NC; j++) {
        if (j + 1 < NC) { load_chunk(j + 1); CP_COMMIT(); CP_WAIT1(); }
        else            { CP_WAIT0(); }
        __syncthreads();

        uint32_t bp = base + (j & 1) * BUF_SZ;
        #pragma unroll
        for (int ks = 0; ks < 4; ks++) {
            const uint32_t colb = (uint32_t)(ks * 32 + (lane >> 4) * 16);
            uint32_t a_hi[4], a_lo[4];
            {
                uint32_t off = sw128((uint32_t)((wm * 16 + (lane & 15)) * 128) + colb);
                ldsm4(a_hi, bp + OFF_AHI + off);
                ldsm4(a_lo, bp + OFF_ALO + off);
            }
            uint32_t bh[2][4], bl[2][4];
            #pragma unroll
            for (int jp = 0; jp < 2; jp++) {
                uint32_t off = sw128((uint32_t)((wn * 32 + jp * 16 + (lane & 15)) * 128) + colb);
                ldsm4(bh[jp], bp + OFF_BHI + off);
                ldsm4(bl[jp], bp + OFF_BLO + off);
            }
            #pragma unroll
            for (int jj = 0; jj < 4; jj++) {
                int jp = jj >> 1, sel = jj & 1;
                uint32_t bh0 = bh[jp][sel], bh1 = bh[jp][sel + 2];
                uint32_t bl0 = bl[jp][sel], bl1 = bl[jp][sel + 2];
                mma_bf16(acc[jj], a_hi, bh0, bh1);
                mma_bf16(acc[jj], a_lo, bh0, bh1);
                mma_bf16(acc[jj], a_hi, bl0, bl1);
            }
        }
        __syncthreads();
    }

    // registers -> zs[row][col], pitch 132  (C-fragment mapping of m16n8k16)
    #pragma unroll
    for (int jj = 0; jj < 4; jj++)
        #pragma unroll
        for (int k4 = 0; k4 < 4; k4++) {
            int r = wm * 16 + (lane >> 2) + ((k4 >> 1) ? 8 : 0);
            int c = wn * 32 + jj * 8 + (lane & 3) * 2 + (k4 & 1);
            zs[r * 132 + c] = acc[jj][k4];
        }
    __syncthreads();

    if (P1) {
        size_t r0 = (size_t)bm * 64;
        int nl = tid & 127, rg = tid >> 7;         // 4 row groups x 16 rows
        int n0 = nb * 128;
        float bz = bias[n0 + nl];
        #pragma unroll 4
        for (int i = 0; i < 16; i++) {
            int rl = rg * 16 + i;
            g_Zpre[(r0 + rl) * H4 + n0 + nl] = zs[rl * 132 + nl] + bz;
        }
    } else {
        int nl = lane;
        int n = nb * 32 + nl;
        #pragma unroll
        for (int it = 0; it < 4; it++) {
            int bl = wid + it * 16;                 // local row 0..63
            int b = bm * 64 + bl;
            const float* zp = g_Zpre + ((size_t)t * BB + b) * H4;
            float vi = zs[bl * 132 +  0 + nl] + zp[0 * HH + n];
            float vf = zs[bl * 132 + 32 + nl] + zp[1 * HH + n];
            float vg = zs[bl * 132 + 64 + nl] + zp[2 * HH + n];
            float vo = zs[bl * 132 + 96 + nl] + zp[3 * HH + n];
            float ig = sigf(vi), fg = sigf(vf);
            float gg = tanhfast(vg), og = sigf(vo);
            int ci = b * HH + n;
            float cn = fg * g_c[ci] + ig * gg;
            g_c[ci] = cn;
            float h = og * tanhfast(cn);
            out[(size_t)b * TT * HH + (size_t)t * HH + n] = h;
            __nv_bfloat16 hi, lo; split2(h, hi, lo);
            g_hhi[t & 1][ci] = hi; g_hlo[t & 1][ci] = lo;
        }
    }
}

// ---------------------------------------------------------------------------
extern "C" void kernel_launch(void* const* d_in, const int* in_sizes, int n_in,
                              void* d_out, int out_size)
{
    (void)in_sizes; (void)n_in; (void)out_size;
    const float* X    = (const float*)d_in[0];   // embed_words [B][T][D]
    const float* W    = (const float*)d_in[2];   // [D+H][4H]  (d_in[1]=lengths unused)
    const float* bias = (const float*)d_in[3];   // [4H]
    float* out        = (float*)d_out;           // [B][T][H]

    cudaFuncSetAttribute(mma_kernel<true>,  cudaFuncAttributeMaxDynamicSharedMemorySize, SMEM_BYTES);
    cudaFuncSetAttribute(mma_kernel<false>, cudaFuncAttributeMaxDynamicSharedMemorySize, SMEM_BYTES);

    convert_X<<<TT * BB, KP1>>>(X);
    transW<<<dim3(74, 256), dim3(32, 8)>>>(W);
    mma_kernel<true><<<dim3(64, 256), 512, SMEM_BYTES>>>(nullptr, bias, 0);
    lstm_step0<<<(BB * HH) / 256, 256>>>(out);
    for (int t = 1; t < TT; t++)
        mma_kernel<false><<<dim3(64, 2), 512, SMEM_BYTES>>>(out, nullptr, t);
}

// round 9
// speedup vs baseline: 4.4349x; 1.3758x over previous
#include <cuda_runtime.h>
#include <cuda_fp16.h>
#include <cstdint>
#include <math.h>

#define BB 128
#define TT 128
#define DD 300
#define HH 2048
#define H4 8192
#define KP1 320
#define LOSCALE 2048.0f
#define INV_LOSCALE (1.0f / 2048.0f)

// ---- device scratch (no allocation in kernel_launch) ----
__device__ float g_Zpre[(size_t)TT * BB * H4];   // x@W1 + bias, [t*BB+b][4H]
__device__ float g_c[BB * HH];
__device__ __half g_Xhi[(size_t)TT * BB * KP1];
__device__ __half g_Xlo[(size_t)TT * BB * KP1];   // (x - hi) * 2048
__device__ __half g_W1h[(size_t)H4 * KP1];        // W[0:300,:]^T padded, [n][k], fp16
__device__ __half g_Whh[(size_t)H4 * HH];         // W[300:,:]^T, [n][k], fp16
__device__ __half g_hhi[2][BB * HH];              // double-buffered h split
__device__ __half g_hlo[2][BB * HH];              // (h - hi) * 2048

// ---- helpers (base sm_100 ISA: cp.async + ldmatrix + mma.sync) ----
__device__ __forceinline__ uint32_t smem_u32(const void* p) {
    uint32_t a;
    asm("{ .reg .u64 t; cvta.to.shared.u64 t, %1; cvt.u32.u64 %0, t; }" : "=r"(a) : "l"(p));
    return a;
}
__device__ __forceinline__ void cpa16(uint32_t dst, const void* src) {
    asm volatile("cp.async.cg.shared.global [%0], [%1], 16;" :: "r"(dst), "l"(src) : "memory");
}
#define CP_COMMIT() asm volatile("cp.async.commit_group;" ::: "memory")
#define CP_WAIT1()  asm volatile("cp.async.wait_group 1;" ::: "memory")
#define CP_WAIT0()  asm volatile("cp.async.wait_group 0;" ::: "memory")

__device__ __forceinline__ void ldsm4(uint32_t* r, uint32_t addr) {
    asm volatile("ldmatrix.sync.aligned.m8n8.x4.shared.b16 {%0,%1,%2,%3}, [%4];"
                 : "=r"(r[0]), "=r"(r[1]), "=r"(r[2]), "=r"(r[3]) : "r"(addr));
}
__device__ __forceinline__ void mma_f16(float* c, const uint32_t* a,
                                        uint32_t b0, uint32_t b1) {
    asm volatile("mma.sync.aligned.m16n8k16.row.col.f32.f16.f16.f32 "
                 "{%0,%1,%2,%3}, {%4,%5,%6,%7}, {%8,%9}, {%0,%1,%2,%3};"
                 : "+f"(c[0]), "+f"(c[1]), "+f"(c[2]), "+f"(c[3])
                 : "r"(a[0]), "r"(a[1]), "r"(a[2]), "r"(a[3]), "r"(b0), "r"(b1));
}
__device__ __forceinline__ uint32_t sw128(uint32_t x) { return x ^ ((x >> 3) & 0x70); }

// smem chunk buffer: A(64 rows x 128B) hi/lo + B(128 rows x 128B) single
#define OFF_AHI 0
#define OFF_ALO 8192
#define OFF_B   16384
#define BUF_SZ  32768
#define SMEM_BYTES (1024 + 2 * BUF_SZ)

// ---- activations (overflow-safe) ----
__device__ __forceinline__ float sigf(float x) {
    return __fdividef(1.f, 1.f + __expf(-x));
}
__device__ __forceinline__ float tanhfast(float x) {
    float e = __expf(-2.f * fabsf(x));
    return copysignf(__fdividef(1.f - e, 1.f + e), x);
}
__device__ __forceinline__ void split2h(float v, __half& hi, __half& lo) {
    hi = __float2half_rn(v);
    lo = __float2half_rn((v - __half2float(hi)) * LOSCALE);
}

// ---- prep: split X into fp16 hi/lo rows [r=t*BB+b][KP1], zero-padded K ----
__global__ void __launch_bounds__(KP1) convert_X(const float* __restrict__ X)
{
    int r = blockIdx.x, k = threadIdx.x;
    int t = r >> 7, b = r & (BB - 1);
    float v = (k < DD) ? X[((size_t)b * TT + t) * DD + k] : 0.f;
    __half hi, lo; split2h(v, hi, lo);
    size_t o = (size_t)r * KP1 + k;
    g_Xhi[o] = hi; g_Xlo[o] = lo;
}

// ---- prep: transpose W (fp16) into W1t [n][0..320) and Wht [n][0..2048) ----
__global__ void __launch_bounds__(256) transW(const float* __restrict__ W)
{
    __shared__ float tile[32][33];
    int tx = threadIdx.x, ty = threadIdx.y;   // 32 x 8
    int k_t = blockIdx.x * 32;                // 74 tiles over kk in [0,2368)
    int n_t = blockIdx.y * 32;
    #pragma unroll
    for (int i = 0; i < 4; i++) {
        int kk = k_t + ty + i * 8;
        float v = 0.f;
        if (kk < KP1) { if (kk < DD) v = W[(size_t)kk * H4 + n_t + tx]; }
        else           v = W[(size_t)(kk - 20) * H4 + n_t + tx];   // kk-320+300
        tile[ty + i * 8][tx] = v;
    }
    __syncthreads();
    #pragma unroll
    for (int i = 0; i < 4; i++) {
        int n  = n_t + ty + i * 8;
        int kk = k_t + tx;
        __half wh = __float2half_rn(tile[tx][ty + i * 8]);
        if (kk < KP1) g_W1h[(size_t)n * KP1 + kk] = wh;
        else          g_Whh[(size_t)n * HH + (kk - KP1)] = wh;
    }
}

// ---- step 0: h0 = 0 -> c = i*g, h = o*tanh(c); also seeds g_h[0] ----
__global__ void __launch_bounds__(256) lstm_step0(float* __restrict__ out)
{
    int idx = blockIdx.x * blockDim.x + threadIdx.x;   // [0, B*H)
    int b = idx >> 11, n = idx & (HH - 1);
    const float* zp = g_Zpre + (size_t)b * H4;          // r = b at t=0
    float cn = sigf(zp[n]) * tanhfast(zp[2 * HH + n]);
    float h  = sigf(zp[3 * HH + n]) * tanhfast(cn);
    g_c[idx] = cn;
    out[(size_t)b * TT * HH + n] = h;
    __half hi, lo; split2h(h, hi, lo);
    g_hhi[0][idx] = hi; g_hlo[0][idx] = lo;
}

// ---------------------------------------------------------------------------
// fp16 mma.sync GEMM, tile M=64 x N=128, K chunks of 64.
// 2-product scheme: z = Ah*W + (Alo2048*W)/2048 (separate fp32 accumulators).
// 512 threads = 16 warps (4m x 4n), warp tile 16x32.
// P1: Zpre tile = X @ W1t^T + bias.   step: z = h @ Wht^T + fused LSTM epilogue.
// ---------------------------------------------------------------------------
template<bool P1>
__global__ void __launch_bounds__(512, 1) mma_kernel(
    float* __restrict__ out, const float* __restrict__ bias, int t)
{
    extern __shared__ __align__(16) char dsm[];
    const uint32_t raw  = smem_u32(dsm);
    const uint32_t base = (raw + 1023) & ~1023u;
    float* zs = (float*)(dsm + (base - raw));      // reused post-GEMM, pitch 132

    const int tid = threadIdx.x, wid = tid >> 5, lane = tid & 31;
    const int wm = wid >> 2, wn = wid & 3;         // warp grid 4m x 4n
    const int NC = P1 ? 5 : 32;
    const int nb = blockIdx.x;                     // n tile
    const int bm = blockIdx.y;                     // m tile

    const __half *Ahi, *Alo, *Bh;
    size_t astr, bstr;
    if (P1) {
        size_t r0 = (size_t)bm * 64;
        Ahi = g_Xhi + r0 * KP1; Alo = g_Xlo + r0 * KP1; astr = KP1;
        Bh = g_W1h; bstr = KP1;
    } else {
        int pb = (t - 1) & 1;
        Ahi = g_hhi[pb] + (size_t)bm * 64 * HH;
        Alo = g_hlo[pb] + (size_t)bm * 64 * HH;
        astr = HH;
        Bh = g_Whh; bstr = HH;
    }

    auto load_chunk = [&](int j) {
        uint32_t bp = base + (j & 1) * BUF_SZ;
        int kb = j * 128;                          // K byte offset (64 fp16)
        {                                          // A: 64 rows x 8 x16B, 512 thr
            int row = tid >> 3, q = tid & 7;
            uint32_t so = sw128((uint32_t)(row * 128 + q * 16));
            size_t go = (size_t)row * astr * 2 + kb + q * 16;
            cpa16(bp + OFF_AHI + so, (const char*)Ahi + go);
            cpa16(bp + OFF_ALO + so, (const char*)Alo + go);
        }
        #pragma unroll
        for (int i = 0; i < 2; i++) {              // B: 128 rows x 8 x16B
            int e = tid + i * 512; int c = e >> 3, q = e & 7;
            int ng = P1 ? (nb * 128 + c) : ((c >> 5) * HH + nb * 32 + (c & 31));
            uint32_t so = sw128((uint32_t)(c * 128 + q * 16));
            size_t go = (size_t)ng * bstr * 2 + kb + q * 16;
            cpa16(bp + OFF_B + so, (const char*)Bh + go);
        }
    };

    float acc[4][4], acl[4][4];
    #pragma unroll
    for (int j = 0; j < 4; j++)
        #pragma unroll
        for (int k = 0; k < 4; k++) { acc[j][k] = 0.f; acl[j][k] = 0.f; }

    load_chunk(0); CP_COMMIT();

    for (int j = 0; j < NC; j++) {
        if (j + 1 < NC) { load_chunk(j + 1); CP_COMMIT(); CP_WAIT1(); }
        else            { CP_WAIT0(); }
        __syncthreads();

        uint32_t bp = base + (j & 1) * BUF_SZ;
        #pragma unroll
        for (int ks = 0; ks < 4; ks++) {
            const uint32_t colb = (uint32_t)(ks * 32 + (lane >> 4) * 16);
            uint32_t a_hi[4], a_lo[4];
            {
                uint32_t off = sw128((uint32_t)((wm * 16 + (lane & 15)) * 128) + colb);
                ldsm4(a_hi, bp + OFF_AHI + off);
                ldsm4(a_lo, bp + OFF_ALO + off);
            }
            uint32_t bh[2][4];
            #pragma unroll
            for (int jp = 0; jp < 2; jp++) {
                uint32_t off = sw128((uint32_t)((wn * 32 + jp * 16 + (lane & 15)) * 128) + colb);
                ldsm4(bh[jp], bp + OFF_B + off);
            }
            #pragma unroll
            for (int jj = 0; jj < 4; jj++) {
                int jp = jj >> 1, sel = jj & 1;
                uint32_t b0 = bh[jp][sel], b1 = bh[jp][sel + 2];
                mma_f16(acc[jj], a_hi, b0, b1);
                mma_f16(acl[jj], a_lo, b0, b1);
            }
        }
        __syncthreads();
    }

    // registers -> zs[row][col], pitch 132  (C-fragment mapping of m16n8k16)
    #pragma unroll
    for (int jj = 0; jj < 4; jj++)
        #pragma unroll
        for (int k4 = 0; k4 < 4; k4++) {
            int r = wm * 16 + (lane >> 2) + ((k4 >> 1) ? 8 : 0);
            int c = wn * 32 + jj * 8 + (lane & 3) * 2 + (k4 & 1);
            zs[r * 132 + c] = acc[jj][k4] + acl[jj][k4] * INV_LOSCALE;
        }
    __syncthreads();

    if (P1) {
        size_t r0 = (size_t)bm * 64;
        int nl = tid & 127, rg = tid >> 7;         // 4 row groups x 16 rows
        int n0 = nb * 128;
        float bz = bias[n0 + nl];
        #pragma unroll 4
        for (int i = 0; i < 16; i++) {
            int rl = rg * 16 + i;
            g_Zpre[(r0 + rl) * H4 + n0 + nl] = zs[rl * 132 + nl] + bz;
        }
    } else {
        int nl = lane;
        int n = nb * 32 + nl;
        #pragma unroll
        for (int it = 0; it < 4; it++) {
            int bl = wid + it * 16;                 // local row 0..63
            int b = bm * 64 + bl;
            const float* zp = g_Zpre + ((size_t)t * BB + b) * H4;
            float vi = zs[bl * 132 +  0 + nl] + zp[0 * HH + n];
            float vf = zs[bl * 132 + 32 + nl] + zp[1 * HH + n];
            float vg = zs[bl * 132 + 64 + nl] + zp[2 * HH + n];
            float vo = zs[bl * 132 + 96 + nl] + zp[3 * HH + n];
            float ig = sigf(vi), fg = sigf(vf);
            float gg = tanhfast(vg), og = sigf(vo);
            int ci = b * HH + n;
            float cn = fg * g_c[ci] + ig * gg;
            g_c[ci] = cn;
            float h = og * tanhfast(cn);
            out[(size_t)b * TT * HH + (size_t)t * HH + n] = h;
            __half hi, lo; split2h(h, hi, lo);
            g_hhi[t & 1][ci] = hi; g_hlo[t & 1][ci] = lo;
        }
    }
}

// ---------------------------------------------------------------------------
extern "C" void kernel_launch(void* const* d_in, const int* in_sizes, int n_in,
                              void* d_out, int out_size)
{
    (void)in_sizes; (void)n_in; (void)out_size;
    const float* X    = (const float*)d_in[0];   // embed_words [B][T][D]
    const float* W    = (const float*)d_in[2];   // [D+H][4H]  (d_in[1]=lengths unused)
    const float* bias = (const float*)d_in[3];   // [4H]
    float* out        = (float*)d_out;           // [B][T][H]

    cudaFuncSetAttribute(mma_kernel<true>,  cudaFuncAttributeMaxDynamicSharedMemorySize, SMEM_BYTES);
    cudaFuncSetAttribute(mma_kernel<false>, cudaFuncAttributeMaxDynamicSharedMemorySize, SMEM_BYTES);

    convert_X<<<TT * BB, KP1>>>(X);
    transW<<<dim3(74, 256), dim3(32, 8)>>>(W);
    mma_kernel<true><<<dim3(64, 256), 512, SMEM_BYTES>>>(nullptr, bias, 0);
    lstm_step0<<<(BB * HH) / 256, 256>>>(out);
    for (int t = 1; t < TT; t++)
        mma_kernel<false><<<dim3(64, 2), 512, SMEM_BYTES>>>(out, nullptr, t);
}

// round 10
// speedup vs baseline: 6.0688x; 1.3684x over previous
#include <cuda_runtime.h>
#include <cuda_fp16.h>
#include <cstdint>
#include <math.h>

#define BB 128
#define TT 128
#define DD 300
#define HH 2048
#define H4 8192
#define KP1 320

// ---- device scratch (no allocation in kernel_launch) ----
__device__ float g_Zpre[(size_t)TT * BB * H4];   // x@W1 + bias, [t*BB+b][4H]
__device__ float g_c[BB * HH];
__device__ __half g_Xh[(size_t)TT * BB * KP1];    // x fp16, [r=t*BB+b][KP1]
__device__ __half g_W1h[(size_t)H4 * KP1];        // W[0:300,:]^T padded, [n][k], fp16
__device__ __half g_Whh[(size_t)H4 * HH];         // W[300:,:]^T, [n][k], fp16
__device__ __half g_hh[2][BB * HH];               // double-buffered h fp16

// ---- helpers (base sm_100 ISA: cp.async + ldmatrix + mma.sync) ----
__device__ __forceinline__ uint32_t smem_u32(const void* p) {
    uint32_t a;
    asm("{ .reg .u64 t; cvta.to.shared.u64 t, %1; cvt.u32.u64 %0, t; }" : "=r"(a) : "l"(p));
    return a;
}
__device__ __forceinline__ void cpa16(uint32_t dst, const void* src) {
    asm volatile("cp.async.cg.shared.global [%0], [%1], 16;" :: "r"(dst), "l"(src) : "memory");
}
#define CP_COMMIT() asm volatile("cp.async.commit_group;" ::: "memory")
#define CP_WAIT1()  asm volatile("cp.async.wait_group 1;" ::: "memory")
#define CP_WAIT0()  asm volatile("cp.async.wait_group 0;" ::: "memory")

__device__ __forceinline__ void ldsm4(uint32_t* r, uint32_t addr) {
    asm volatile("ldmatrix.sync.aligned.m8n8.x4.shared.b16 {%0,%1,%2,%3}, [%4];"
                 : "=r"(r[0]), "=r"(r[1]), "=r"(r[2]), "=r"(r[3]) : "r"(addr));
}
__device__ __forceinline__ void mma_f16(float* c, const uint32_t* a,
                                        uint32_t b0, uint32_t b1) {
    asm volatile("mma.sync.aligned.m16n8k16.row.col.f32.f16.f16.f32 "
                 "{%0,%1,%2,%3}, {%4,%5,%6,%7}, {%8,%9}, {%0,%1,%2,%3};"
                 : "+f"(c[0]), "+f"(c[1]), "+f"(c[2]), "+f"(c[3])
                 : "r"(a[0]), "r"(a[1]), "r"(a[2]), "r"(a[3]), "r"(b0), "r"(b1));
}
__device__ __forceinline__ uint32_t sw128(uint32_t x) { return x ^ ((x >> 3) & 0x70); }

// smem chunk buffer: A(64 rows x 128B) + B(128 rows x 128B)
#define OFF_A   0
#define OFF_B   8192
#define BUF_SZ  24576
#define SMEM_BYTES (1024 + 2 * BUF_SZ)

// ---- activations (overflow-safe) ----
__device__ __forceinline__ float sigf(float x) {
    return __fdividef(1.f, 1.f + __expf(-x));
}
__device__ __forceinline__ float tanhfast(float x) {
    float e = __expf(-2.f * fabsf(x));
    return copysignf(__fdividef(1.f - e, 1.f + e), x);
}

// ---- prep: X -> fp16 rows [r=t*BB+b][KP1], zero-padded K ----
__global__ void __launch_bounds__(KP1) convert_X(const float* __restrict__ X)
{
    int r = blockIdx.x, k = threadIdx.x;
    int t = r >> 7, b = r & (BB - 1);
    float v = (k < DD) ? X[((size_t)b * TT + t) * DD + k] : 0.f;
    g_Xh[(size_t)r * KP1 + k] = __float2half_rn(v);
}

// ---- prep: transpose W (fp16) into W1t [n][0..320) and Wht [n][0..2048) ----
__global__ void __launch_bounds__(256) transW(const float* __restrict__ W)
{
    __shared__ float tile[32][33];
    int tx = threadIdx.x, ty = threadIdx.y;   // 32 x 8
    int k_t = blockIdx.x * 32;                // 74 tiles over kk in [0,2368)
    int n_t = blockIdx.y * 32;
    #pragma unroll
    for (int i = 0; i < 4; i++) {
        int kk = k_t + ty + i * 8;
        float v = 0.f;
        if (kk < KP1) { if (kk < DD) v = W[(size_t)kk * H4 + n_t + tx]; }
        else           v = W[(size_t)(kk - 20) * H4 + n_t + tx];   // kk-320+300
        tile[ty + i * 8][tx] = v;
    }
    __syncthreads();
    #pragma unroll
    for (int i = 0; i < 4; i++) {
        int n  = n_t + ty + i * 8;
        int kk = k_t + tx;
        __half wh = __float2half_rn(tile[tx][ty + i * 8]);
        if (kk < KP1) g_W1h[(size_t)n * KP1 + kk] = wh;
        else          g_Whh[(size_t)n * HH + (kk - KP1)] = wh;
    }
}

// ---- step 0: h0 = 0 -> c = i*g, h = o*tanh(c); also seeds g_hh[0] ----
__global__ void __launch_bounds__(256) lstm_step0(float* __restrict__ out)
{
    int idx = blockIdx.x * blockDim.x + threadIdx.x;   // [0, B*H)
    int b = idx >> 11, n = idx & (HH - 1);
    const float* zp = g_Zpre + (size_t)b * H4;          // r = b at t=0
    float cn = sigf(zp[n]) * tanhfast(zp[2 * HH + n]);
    float h  = sigf(zp[3 * HH + n]) * tanhfast(cn);
    g_c[idx] = cn;
    out[(size_t)b * TT * HH + n] = h;
    g_hh[0][idx] = __float2half_rn(h);
}

// ---------------------------------------------------------------------------
// fp16 mma.sync GEMM, tile M=64 x N=128, K chunks of 64, single product.
// 512 threads = 16 warps (4m x 4n), warp tile 16x32, acc[4][4].
// P1: Zpre tile = X @ W1t^T + bias.   step: z = h @ Wht^T + fused LSTM epilogue.
// ---------------------------------------------------------------------------
template<bool P1>
__global__ void __launch_bounds__(512, 1) mma_kernel(
    float* __restrict__ out, const float* __restrict__ bias, int t)
{
    extern __shared__ __align__(16) char dsm[];
    const uint32_t raw  = smem_u32(dsm);
    const uint32_t base = (raw + 1023) & ~1023u;
    float* zs = (float*)(dsm + (base - raw));      // reused post-GEMM, pitch 132

    const int tid = threadIdx.x, wid = tid >> 5, lane = tid & 31;
    const int wm = wid >> 2, wn = wid & 3;         // warp grid 4m x 4n
    const int NC = P1 ? 5 : 32;
    const int nb = blockIdx.x;                     // n tile
    const int bm = blockIdx.y;                     // m tile

    const __half *Ah, *Bh;
    size_t astr, bstr;
    if (P1) {
        size_t r0 = (size_t)bm * 64;
        Ah = g_Xh + r0 * KP1; astr = KP1;
        Bh = g_W1h; bstr = KP1;
    } else {
        Ah = g_hh[(t - 1) & 1] + (size_t)bm * 64 * HH;
        astr = HH;
        Bh = g_Whh; bstr = HH;
    }

    auto load_chunk = [&](int j) {
        uint32_t bp = base + (j & 1) * BUF_SZ;
        int kb = j * 128;                          // K byte offset (64 fp16)
        {                                          // A: 64 rows x 8 x16B
            int row = tid >> 3, q = tid & 7;
            uint32_t so = sw128((uint32_t)(row * 128 + q * 16));
            cpa16(bp + OFF_A + so, (const char*)Ah + (size_t)row * astr * 2 + kb + q * 16);
        }
        #pragma unroll
        for (int i = 0; i < 2; i++) {              // B: 128 rows x 8 x16B
            int e = tid + i * 512; int c = e >> 3, q = e & 7;
            int ng = P1 ? (nb * 128 + c) : ((c >> 5) * HH + nb * 32 + (c & 31));
            uint32_t so = sw128((uint32_t)(c * 128 + q * 16));
            cpa16(bp + OFF_B + so, (const char*)Bh + (size_t)ng * bstr * 2 + kb + q * 16);
        }
    };

    float acc[4][4];
    #pragma unroll
    for (int j = 0; j < 4; j++)
        #pragma unroll
        for (int k = 0; k < 4; k++) acc[j][k] = 0.f;

    load_chunk(0); CP_COMMIT();

    for (int j = 0; j < NC; j++) {
        if (j + 1 < NC) { load_chunk(j + 1); CP_COMMIT(); CP_WAIT1(); }
        else            { CP_WAIT0(); }
        __syncthreads();

        uint32_t bp = base + (j & 1) * BUF_SZ;
        #pragma unroll
        for (int ks = 0; ks < 4; ks++) {
            const uint32_t colb = (uint32_t)(ks * 32 + (lane >> 4) * 16);
            uint32_t av[4];
            {
                uint32_t off = sw128((uint32_t)((wm * 16 + (lane & 15)) * 128) + colb);
                ldsm4(av, bp + OFF_A + off);
            }
            uint32_t bh[2][4];
            #pragma unroll
            for (int jp = 0; jp < 2; jp++) {
                uint32_t off = sw128((uint32_t)((wn * 32 + jp * 16 + (lane & 15)) * 128) + colb);
                ldsm4(bh[jp], bp + OFF_B + off);
            }
            #pragma unroll
            for (int jj = 0; jj < 4; jj++) {
                int jp = jj >> 1, sel = jj & 1;
                mma_f16(acc[jj], av, bh[jp][sel], bh[jp][sel + 2]);
            }
        }
        __syncthreads();
    }

    // registers -> zs[row][col], pitch 132  (C-fragment mapping of m16n8k16)
    #pragma unroll
    for (int jj = 0; jj < 4; jj++)
        #pragma unroll
        for (int k4 = 0; k4 < 4; k4++) {
            int r = wm * 16 + (lane >> 2) + ((k4 >> 1) ? 8 : 0);
            int c = wn * 32 + jj * 8 + (lane & 3) * 2 + (k4 & 1);
            zs[r * 132 + c] = acc[jj][k4];
        }
    __syncthreads();

    if (P1) {
        size_t r0 = (size_t)bm * 64;
        int nl = tid & 127, rg = tid >> 7;         // 4 row groups x 16 rows
        int n0 = nb * 128;
        float bz = bias[n0 + nl];
        #pragma unroll 4
        for (int i = 0; i < 16; i++) {
            int rl = rg * 16 + i;
            g_Zpre[(r0 + rl) * H4 + n0 + nl] = zs[rl * 132 + nl] + bz;
        }
    } else {
        int nl = lane;
        int n = nb * 32 + nl;
        #pragma unroll
        for (int it = 0; it < 4; it++) {
            int bl = wid + it * 16;                 // local row 0..63
            int b = bm * 64 + bl;
            const float* zp = g_Zpre + ((size_t)t * BB + b) * H4;
            float vi = zs[bl * 132 +  0 + nl] + zp[0 * HH + n];
            float vf = zs[bl * 132 + 32 + nl] + zp[1 * HH + n];
            float vg = zs[bl * 132 + 64 + nl] + zp[2 * HH + n];
            float vo = zs[bl * 132 + 96 + nl] + zp[3 * HH + n];
            float ig = sigf(vi), fg = sigf(vf);
            float gg = tanhfast(vg), og = sigf(vo);
            int ci = b * HH + n;
            float cn = fg * g_c[ci] + ig * gg;
            g_c[ci] = cn;
            float h = og * tanhfast(cn);
            out[(size_t)b * TT * HH + (size_t)t * HH + n] = h;
            g_hh[t & 1][ci] = __float2half_rn(h);
        }
    }
}

// ---------------------------------------------------------------------------
extern "C" void kernel_launch(void* const* d_in, const int* in_sizes, int n_in,
                              void* d_out, int out_size)
{
    (void)in_sizes; (void)n_in; (void)out_size;
    const float* X    = (const float*)d_in[0];   // embed_words [B][T][D]
    const float* W    = (const float*)d_in[2];   // [D+H][4H]  (d_in[1]=lengths unused)
    const float* bias = (const float*)d_in[3];   // [4H]
    float* out        = (float*)d_out;           // [B][T][H]

    cudaFuncSetAttribute(mma_kernel<true>,  cudaFuncAttributeMaxDynamicSharedMemorySize, SMEM_BYTES);
    cudaFuncSetAttribute(mma_kernel<false>, cudaFuncAttributeMaxDynamicSharedMemorySize, SMEM_BYTES);

    convert_X<<<TT * BB, KP1>>>(X);
    transW<<<dim3(74, 256), dim3(32, 8)>>>(W);
    mma_kernel<true><<<dim3(64, 256), 512, SMEM_BYTES>>>(nullptr, bias, 0);
    lstm_step0<<<(BB * HH) / 256, 256>>>(out);
    for (int t = 1; t < TT; t++)
        mma_kernel<false><<<dim3(64, 2), 512, SMEM_BYTES>>>(out, nullptr, t);
}

// round 12
// speedup vs baseline: 6.2551x; 1.0307x over previous
#include <cuda_runtime.h>
#include <cuda_fp16.h>
#include <cstdint>
#include <math.h>

#define BB 128
#define TT 128
#define DD 300
#define HH 2048
#define H4 8192
#define KP1 320

// ---- device scratch (no allocation in kernel_launch) ----
__device__ float g_Zpre[(size_t)TT * BB * H4];   // x@W1 + bias, [t*BB+b][4H]
__device__ __half g_Xh[(size_t)TT * BB * KP1];    // x fp16, [r=t*BB+b][KP1]
__device__ __half g_W1h[(size_t)H4 * KP1];        // W[0:300,:]^T padded, [n][k], fp16
__device__ __half g_Whh[(size_t)H4 * HH];         // W[300:,:]^T, [n][k], fp16
__device__ __half g_hh[2][BB * HH];               // double-buffered h fp16
__device__ unsigned g_cnt = 0;                    // grid barrier
__device__ unsigned g_gen = 0;

// ---- helpers (base sm_100 ISA: cp.async + ldmatrix + mma.sync) ----
__device__ __forceinline__ uint32_t smem_u32(const void* p) {
    uint32_t a;
    asm("{ .reg .u64 t; cvta.to.shared.u64 t, %1; cvt.u32.u64 %0, t; }" : "=r"(a) : "l"(p));
    return a;
}
__device__ __forceinline__ void cpa16(uint32_t dst, const void* src) {
    asm volatile("cp.async.cg.shared.global [%0], [%1], 16;" :: "r"(dst), "l"(src) : "memory");
}
#define CP_COMMIT() asm volatile("cp.async.commit_group;" ::: "memory")
#define CP_WAIT1()  asm volatile("cp.async.wait_group 1;" ::: "memory")
#define CP_WAIT0()  asm volatile("cp.async.wait_group 0;" ::: "memory")

__device__ __forceinline__ void ldsm4(uint32_t* r, uint32_t addr) {
    asm volatile("ldmatrix.sync.aligned.m8n8.x4.shared.b16 {%0,%1,%2,%3}, [%4];"
                 : "=r"(r[0]), "=r"(r[1]), "=r"(r[2]), "=r"(r[3]) : "r"(addr));
}
__device__ __forceinline__ void mma_f16(float* c, const uint32_t* a,
                                        uint32_t b0, uint32_t b1) {
    asm volatile("mma.sync.aligned.m16n8k16.row.col.f32.f16.f16.f32 "
                 "{%0,%1,%2,%3}, {%4,%5,%6,%7}, {%8,%9}, {%0,%1,%2,%3};"
                 : "+f"(c[0]), "+f"(c[1]), "+f"(c[2]), "+f"(c[3])
                 : "r"(a[0]), "r"(a[1]), "r"(a[2]), "r"(a[3]), "r"(b0), "r"(b1));
}
__device__ __forceinline__ uint32_t sw128(uint32_t x) { return x ^ ((x >> 3) & 0x70); }

// smem: double GEMM buffers + separate Zpre stage; zs overlaps GEMM buffers
#define OFF_A    0
#define OFF_B    8192
#define BUF_SZ   24576
#define ZPRE_OFF (2 * BUF_SZ)                  // 49152
#define SMEM_P1   (1024 + 2 * BUF_SZ)          // phase1: no zpre stage
#define SMEM_PERS (1024 + 2 * BUF_SZ + 32768)  // 82944

// ---- activations (overflow-safe) ----
__device__ __forceinline__ float sigf(float x) {
    return __fdividef(1.f, 1.f + __expf(-x));
}
__device__ __forceinline__ float tanhfast(float x) {
    float e = __expf(-2.f * fabsf(x));
    return copysignf(__fdividef(1.f - e, 1.f + e), x);
}

// ---- grid barrier (all 128 CTAs resident; classic count+generation) ----
__device__ __forceinline__ void grid_sync()
{
    __syncthreads();
    if (threadIdx.x == 0) {
        __threadfence();
        unsigned gen = atomicAdd(&g_gen, 0u);       // read BEFORE arrival
        unsigned arrived = atomicAdd(&g_cnt, 1u);
        if (arrived == 127u) {
            g_cnt = 0;
            __threadfence();
            atomicAdd(&g_gen, 1u);
        } else {
            while (atomicAdd(&g_gen, 0u) == gen) __nanosleep(64);
        }
    }
    __syncthreads();
}

// ---- prep: X -> fp16 rows [r=t*BB+b][KP1], zero-padded K ----
__global__ void __launch_bounds__(KP1) convert_X(const float* __restrict__ X)
{
    int r = blockIdx.x, k = threadIdx.x;
    int t = r >> 7, b = r & (BB - 1);
    float v = (k < DD) ? X[((size_t)b * TT + t) * DD + k] : 0.f;
    g_Xh[(size_t)r * KP1 + k] = __float2half_rn(v);
}

// ---- prep: transpose W (fp16) into W1t [n][0..320) and Wht [n][0..2048) ----
__global__ void __launch_bounds__(256) transW(const float* __restrict__ W)
{
    __shared__ float tile[32][33];
    int tx = threadIdx.x, ty = threadIdx.y;   // 32 x 8
    int k_t = blockIdx.x * 32;                // 74 tiles over kk in [0,2368)
    int n_t = blockIdx.y * 32;
    #pragma unroll
    for (int i = 0; i < 4; i++) {
        int kk = k_t + ty + i * 8;
        float v = 0.f;
        if (kk < KP1) { if (kk < DD) v = W[(size_t)kk * H4 + n_t + tx]; }
        else           v = W[(size_t)(kk - 20) * H4 + n_t + tx];   // kk-320+300
        tile[ty + i * 8][tx] = v;
    }
    __syncthreads();
    #pragma unroll
    for (int i = 0; i < 4; i++) {
        int n  = n_t + ty + i * 8;
        int kk = k_t + tx;
        __half wh = __float2half_rn(tile[tx][ty + i * 8]);
        if (kk < KP1) g_W1h[(size_t)n * KP1 + kk] = wh;
        else          g_Whh[(size_t)n * HH + (kk - KP1)] = wh;
    }
}

// ---------------------------------------------------------------------------
// Phase 1: Zpre = X @ W1t^T + bias.  Tile M=64 x N=128, K=320 (5 chunks).
// 512 threads = 16 warps (4m x 4n), warp tile 16x32.
// ---------------------------------------------------------------------------
__global__ void __launch_bounds__(512, 1) phase1_kernel(const float* __restrict__ bias)
{
    extern __shared__ __align__(16) char dsm[];
    const uint32_t raw  = smem_u32(dsm);
    const uint32_t base = (raw + 1023) & ~1023u;
    float* zs = (float*)(dsm + (base - raw));      // reused post-GEMM, pitch 132

    const int tid = threadIdx.x, wid = tid >> 5, lane = tid & 31;
    const int wm = wid >> 2, wn = wid & 3;
    const int nb = blockIdx.x;
    const size_t r0 = (size_t)blockIdx.y * 64;

    const __half* Ah = g_Xh + r0 * KP1;
    const __half* Bh = g_W1h;

    auto load_chunk = [&](int j) {
        uint32_t bp = base + (j & 1) * BUF_SZ;
        int kb = j * 128;
        {
            int row = tid >> 3, q = tid & 7;
            uint32_t so = sw128((uint32_t)(row * 128 + q * 16));
            cpa16(bp + OFF_A + so, (const char*)Ah + (size_t)row * KP1 * 2 + kb + q * 16);
        }
        #pragma unroll
        for (int i = 0; i < 2; i++) {
            int e = tid + i * 512; int c = e >> 3, q = e & 7;
            uint32_t so = sw128((uint32_t)(c * 128 + q * 16));
            cpa16(bp + OFF_B + so,
                  (const char*)Bh + (size_t)(nb * 128 + c) * KP1 * 2 + kb + q * 16);
        }
    };

    float acc[4][4];
    #pragma unroll
    for (int j = 0; j < 4; j++)
        #pragma unroll
        for (int k = 0; k < 4; k++) acc[j][k] = 0.f;

    load_chunk(0); CP_COMMIT();
    for (int j = 0; j < 5; j++) {
        if (j + 1 < 5) { load_chunk(j + 1); CP_COMMIT(); CP_WAIT1(); }
        else           { CP_WAIT0(); }
        __syncthreads();
        uint32_t bp = base + (j & 1) * BUF_SZ;
        #pragma unroll
        for (int ks = 0; ks < 4; ks++) {
            const uint32_t colb = (uint32_t)(ks * 32 + (lane >> 4) * 16);
            uint32_t av[4];
            ldsm4(av, bp + OFF_A + sw128((uint32_t)((wm * 16 + (lane & 15)) * 128) + colb));
            uint32_t bh[2][4];
            #pragma unroll
            for (int jp = 0; jp < 2; jp++)
                ldsm4(bh[jp], bp + OFF_B +
                      sw128((uint32_t)((wn * 32 + jp * 16 + (lane & 15)) * 128) + colb));
            #pragma unroll
            for (int jj = 0; jj < 4; jj++) {
                int jp = jj >> 1, sel = jj & 1;
                mma_f16(acc[jj], av, bh[jp][sel], bh[jp][sel + 2]);
            }
        }
        __syncthreads();
    }

    #pragma unroll
    for (int jj = 0; jj < 4; jj++)
        #pragma unroll
        for (int k4 = 0; k4 < 4; k4++) {
            int r = wm * 16 + (lane >> 2) + ((k4 >> 1) ? 8 : 0);
            int c = wn * 32 + jj * 8 + (lane & 3) * 2 + (k4 & 1);
            zs[r * 132 + c] = acc[jj][k4];
        }
    __syncthreads();

    int nl = tid & 127, rg = tid >> 7;
    int n0 = nb * 128;
    float bz = bias[n0 + nl];
    #pragma unroll 4
    for (int i = 0; i < 16; i++) {
        int rl = rg * 16 + i;
        g_Zpre[(r0 + rl) * H4 + n0 + nl] = zs[rl * 132 + nl] + bz;
    }
}

// ---------------------------------------------------------------------------
// Persistent step kernel: 128 CTAs (nb 0..63, bm 0..1), all T steps in one
// launch with software grid barriers. c lives in registers; Zpre tile is
// cp.async-prefetched into smem during the GEMM.
// ---------------------------------------------------------------------------
__global__ void __launch_bounds__(512, 1) lstm_persistent(float* __restrict__ out)
{
    extern __shared__ __align__(16) char dsm[];
    const uint32_t raw  = smem_u32(dsm);
    const uint32_t base = (raw + 1023) & ~1023u;
    float* zs  = (float*)(dsm + (base - raw));               // pitch 132, post-GEMM
    float* zps = (float*)(dsm + (base - raw) + ZPRE_OFF);    // Zpre stage, pitch 128

    const int tid = threadIdx.x, wid = tid >> 5, lane = tid & 31;
    const int wm = wid >> 2, wn = wid & 3;
    const int nb = blockIdx.x >> 1;            // 0..63
    const int bm = blockIdx.x & 1;             // 0..1
    const int nl = lane;
    const int n  = nb * 32 + nl;

    // ---- step 0 (no GEMM): c0 = i*g, h0 = o*tanh(c0); seed g_hh[0] ----
    float c_reg[4];
    #pragma unroll
    for (int it = 0; it < 4; it++) {
        int bl = wid + it * 16;
        int b  = bm * 64 + bl;
        const float* zp = g_Zpre + (size_t)b * H4;
        float cn = sigf(zp[n]) * tanhfast(zp[2 * HH + n]);
        float h  = sigf(zp[3 * HH + n]) * tanhfast(cn);
        c_reg[it] = cn;
        out[(size_t)b * TT * HH + n] = h;
        g_hh[0][b * HH + n] = __float2half_rn(h);
    }
    grid_sync();

    for (int t = 1; t < TT; t++) {
        const __half* Ah = g_hh[(t - 1) & 1] + (size_t)bm * 64 * HH;

        auto load_chunk = [&](int j) {
            uint32_t bp = base + (j & 1) * BUF_SZ;
            int kb = j * 128;
            {
                int row = tid >> 3, q = tid & 7;
                uint32_t so = sw128((uint32_t)(row * 128 + q * 16));
                cpa16(bp + OFF_A + so, (const char*)Ah + (size_t)row * HH * 2 + kb + q * 16);
            }
            #pragma unroll
            for (int i = 0; i < 2; i++) {
                int e = tid + i * 512; int c = e >> 3, q = e & 7;
                int ng = (c >> 5) * HH + nb * 32 + (c & 31);   // gate-interleaved
                uint32_t so = sw128((uint32_t)(c * 128 + q * 16));
                cpa16(bp + OFF_B + so, (const char*)g_Whh + (size_t)ng * HH * 2 + kb + q * 16);
            }
        };

        float acc[4][4];
        #pragma unroll
        for (int j = 0; j < 4; j++)
            #pragma unroll
            for (int k = 0; k < 4; k++) acc[j][k] = 0.f;

        // chunk 0 + Zpre prefetch share the first commit group
        load_chunk(0);
        {
            const char* zsrc = (const char*)g_Zpre;
            #pragma unroll
            for (int i = 0; i < 4; i++) {
                int e = tid + i * 512;
                int row = e >> 5, u = e & 31;                 // u: gate(2b) x q(3b)
                size_t gb = (((size_t)t * BB + bm * 64 + row) * H4
                             + (size_t)(u >> 3) * HH + nb * 32) * 4 + (u & 7) * 16;
                cpa16(base + ZPRE_OFF + (uint32_t)(row * 512 + u * 16), zsrc + gb);
            }
        }
        CP_COMMIT();

        for (int j = 0; j < 32; j++) {
            if (j + 1 < 32) { load_chunk(j + 1); CP_COMMIT(); CP_WAIT1(); }
            else            { CP_WAIT0(); }
            __syncthreads();
            uint32_t bp = base + (j & 1) * BUF_SZ;
            #pragma unroll
            for (int ks = 0; ks < 4; ks++) {
                const uint32_t colb = (uint32_t)(ks * 32 + (lane >> 4) * 16);
                uint32_t av[4];
                ldsm4(av, bp + OFF_A + sw128((uint32_t)((wm * 16 + (lane & 15)) * 128) + colb));
                uint32_t bh[2][4];
                #pragma unroll
                for (int jp = 0; jp < 2; jp++)
                    ldsm4(bh[jp], bp + OFF_B +
                          sw128((uint32_t)((wn * 32 + jp * 16 + (lane & 15)) * 128) + colb));
                #pragma unroll
                for (int jj = 0; jj < 4; jj++) {
                    int jp = jj >> 1, sel = jj & 1;
                    mma_f16(acc[jj], av, bh[jp][sel], bh[jp][sel + 2]);
                }
            }
            __syncthreads();
        }

        // registers -> zs (pitch 132)
        #pragma unroll
        for (int jj = 0; jj < 4; jj++)
            #pragma unroll
            for (int k4 = 0; k4 < 4; k4++) {
                int r = wm * 16 + (lane >> 2) + ((k4 >> 1) ? 8 : 0);
                int c = wn * 32 + jj * 8 + (lane & 3) * 2 + (k4 & 1);
                zs[r * 132 + c] = acc[jj][k4];
            }
        __syncthreads();

        // fused epilogue: smem Zpre + register c
        #pragma unroll
        for (int it = 0; it < 4; it++) {
            int bl = wid + it * 16;
            int b  = bm * 64 + bl;
            const float* zr = zps + bl * 128;
            float vi = zs[bl * 132 +  0 + nl] + zr[ 0 + nl];
            float vf = zs[bl * 132 + 32 + nl] + zr[32 + nl];
            float vg = zs[bl * 132 + 64 + nl] + zr[64 + nl];
            float vo = zs[bl * 132 + 96 + nl] + zr[96 + nl];
            float ig = sigf(vi), fg = sigf(vf);
            float gg = tanhfast(vg), og = sigf(vo);
            float cn = fg * c_reg[it] + ig * gg;
            c_reg[it] = cn;
            float h = og * tanhfast(cn);
            out[(size_t)b * TT * HH + (size_t)t * HH + n] = h;
            g_hh[t & 1][b * HH + n] = __float2half_rn(h);
        }
        grid_sync();
    }
}

// ---------------------------------------------------------------------------
extern "C" void kernel_launch(void* const* d_in, const int* in_sizes, int n_in,
                              void* d_out, int out_size)
{
    (void)in_sizes; (void)n_in; (void)out_size;
    const float* X    = (const float*)d_in[0];   // embed_words [B][T][D]
    const float* W    = (const float*)d_in[2];   // [D+H][4H]  (d_in[1]=lengths unused)
    const float* bias = (const float*)d_in[3];   // [4H]
    float* out        = (float*)d_out;           // [B][T][H]

    cudaFuncSetAttribute(phase1_kernel,   cudaFuncAttributeMaxDynamicSharedMemorySize, SMEM_P1);
    cudaFuncSetAttribute(lstm_persistent, cudaFuncAttributeMaxDynamicSharedMemorySize, SMEM_PERS);

    convert_X<<<TT * BB, KP1>>>(X);
    transW<<<dim3(74, 256), dim3(32, 8)>>>(W);
    phase1_kernel<<<dim3(64, 256), 512, SMEM_P1>>>(bias);
    lstm_persistent<<<128, 512, SMEM_PERS>>>(out);
}